// round 12
// baseline (speedup 1.0000x reference)
#include <cuda_runtime.h>
#include <cstdint>

// SAG_4861902979729: X_out[i] = sum_{e in [rp[i], rp[i+1])} X[ci[e]]
// X [N=100000, D=100] f32. rp [N+1], ci [E] int32/int64 (runtime-detected).
//
// R12: split each row across TWO WARPS to convert within-LDG wavefront
// replays (~2.07 cyc/wf) into independent cross-LDG wavefronts (~1.0 cyc/wf).
// R10 (asm) and R11 (C++ if/else) proved intra-warp predicated splitting is
// uncompilable cleanly; inter-warp splitting needs no predication at all.
//   warp A: chunks 0..12  (13 float4, 208B of the 400B row)
//   warp B: chunks 13..24 (12 float4, 192B)
// Per neighbor: lines(A)+lines(B) = 4.875 avg wavefronts at cross-LDG pricing
// vs 4 x 2.07 = 8.3 today. Warp pair (2w,2w+1) shares a block so the
// duplicated index cacheline is an L1 hit. Body = proven R4 MLP=4 shape.

#define D_DIM 100

__device__ __forceinline__ void acc_add(float4& a, const float4& v) {
    a.x += v.x; a.y += v.y; a.z += v.z; a.w += v.w;
}

// deg==32 fast path for one half-row: 8 groups x 4 neighbors.
__device__ __forceinline__
float4 gather32_half(const float* __restrict__ X, int my_idx,
                     bool active, size_t off_floats)
{
    float4 acc = make_float4(0.f, 0.f, 0.f, 0.f);
    #pragma unroll
    for (int g = 0; g < 8; g++) {
        const int j0 = __shfl_sync(0xffffffffu, my_idx, g * 4 + 0);
        const int j1 = __shfl_sync(0xffffffffu, my_idx, g * 4 + 1);
        const int j2 = __shfl_sync(0xffffffffu, my_idx, g * 4 + 2);
        const int j3 = __shfl_sync(0xffffffffu, my_idx, g * 4 + 3);
        if (active) {
            const float4 v0 = *(const float4*)(X + (size_t)j0 * D_DIM + off_floats);
            const float4 v1 = *(const float4*)(X + (size_t)j1 * D_DIM + off_floats);
            const float4 v2 = *(const float4*)(X + (size_t)j2 * D_DIM + off_floats);
            const float4 v3 = *(const float4*)(X + (size_t)j3 * D_DIM + off_floats);
            acc.x += (v0.x + v1.x) + (v2.x + v3.x);
            acc.y += (v0.y + v1.y) + (v2.y + v3.y);
            acc.z += (v0.z + v1.z) + (v2.z + v3.z);
            acc.w += (v0.w + v1.w) + (v2.w + v3.w);
        }
    }
    return acc;
}

// Generic path for one half-row (any degree / any index type).
template <typename IT>
__device__ __forceinline__
void sag_row_generic_half(const float* __restrict__ X,
                          const IT* __restrict__ rp,
                          const IT* __restrict__ ci,
                          float* __restrict__ out,
                          int row, int lane, bool active, size_t off_floats)
{
    const long long start = (long long)rp[row];
    const int deg = (int)((long long)rp[row + 1] - start);

    float4 acc = make_float4(0.f, 0.f, 0.f, 0.f);
    for (int k0 = 0; k0 < deg; k0 += 32) {
        const int cnt = min(32, deg - k0);
        int my_idx = 0;
        if (lane < cnt) my_idx = (int)__ldcs(ci + start + k0 + lane);
        for (int k = 0; k < cnt; k++) {
            const int j = __shfl_sync(0xffffffffu, my_idx, k);
            if (active) {
                const float4 v = *(const float4*)(X + (size_t)j * D_DIM + off_floats);
                acc_add(acc, v);
            }
        }
    }
    if (active)
        __stcs((float4*)(out + (size_t)row * D_DIM + off_floats), acc);
}

__global__ __launch_bounds__(256)
void sag_halfrow_kernel(const float* __restrict__ X,
                        const void* __restrict__ rp_raw,
                        const void* __restrict__ ci_raw,
                        float* __restrict__ out,
                        int n)
{
    const int lane  = threadIdx.x & 31;
    const int gwarp = (blockIdx.x * blockDim.x + threadIdx.x) >> 5;
    const int row   = gwarp >> 1;        // two warps per row
    const int half  = gwarp & 1;         // 0: chunks 0..12, 1: chunks 13..24
    if (row >= n) return;

    const int  chunk_base = half ? 13 : 0;
    const int  nchunks    = half ? 12 : 13;
    const bool active     = (lane < nchunks);
    const size_t off_floats = (size_t)(chunk_base + lane) * 4;

    // Runtime index-width probe: two ALIGNED scalar 4B loads (uniform result).
    // int32 rp: words [0,32,64,...] -> w1 != 0
    // int64 rp: words [0,0,32,0,..] -> w1 == 0 && w2 != 0
    const int* rp_words = (const int*)rp_raw;
    const int w1 = __ldg(rp_words + 1);
    const int w2 = __ldg(rp_words + 2);
    const bool is64 = (w1 == 0) && (w2 != 0);

    if (!is64) {
        const int* rp = (const int*)rp_raw;
        const int* ci = (const int*)ci_raw;
        const int start = __ldg(rp + row);
        const int deg   = __ldg(rp + row + 1) - start;

        if (deg == 32) {
            const int my_idx = (int)__ldcs(ci + start + lane);
            const float4 acc = gather32_half(X, my_idx, active, off_floats);
            if (active)
                __stcs((float4*)(out + (size_t)row * D_DIM + off_floats), acc);
        } else {
            sag_row_generic_half<int>(X, rp, ci, out, row, lane,
                                      active, off_floats);
        }
    } else {
        const long long* rp = (const long long*)rp_raw;
        const long long* ci = (const long long*)ci_raw;
        sag_row_generic_half<long long>(X, rp, ci, out, row, lane,
                                        active, off_floats);
    }
}

extern "C" void kernel_launch(void* const* d_in, const int* in_sizes, int n_in,
                              void* d_out, int out_size)
{
    const float* X   = (const float*)d_in[0];
    const void*  rp  = d_in[1];
    const void*  ci  = d_in[2];
    float*       out = (float*)d_out;

    const int n = in_sizes[1] - 1;           // row_pointers has N+1 entries

    const int threads = 256;                  // 8 warps/block = 4 rows/block
    const long long total_warps = 2LL * n;    // two warps per row
    const int blocks = (int)((total_warps * 32 + threads - 1) / threads);

    sag_halfrow_kernel<<<blocks, threads>>>(X, rp, ci, out, n);
}

// round 13
// speedup vs baseline: 1.7462x; 1.7462x over previous
#include <cuda_runtime.h>
#include <cstdint>

// SAG_4861902979729: X_out[i] = sum_{e in [rp[i], rp[i+1])} X[ci[e]]
// X [N=100000, D=100] f32. rp [N+1], ci [E] int32/int64 (runtime-detected).
//
// R13: PERSISTENT GRID. Gather-splitting (R10/R11/R12) is falsified: the
// 25-lane LDG.E.128 over a 400B row (4 lines, ~8.3 cyc/neighbor) is
// wavefront-optimal. Remaining measured slack in the R4 shape:
//  (1) ~10.5 block waves -> ~10us of wave-transition overhead,
//  (2) L1 at 86.6% (not ~98%): rp->ci row-startup chain partially exposed.
// Fix: 888 blocks (6/SM at 38 regs), each warp loops ~14 rows with the
// R8 next-row rp/idx prefetch (which was dead code in R8's 1-row/warp grid).
// Gather body unchanged (proven R4 MLP=4 shape).

#define D_DIM 100
#define VEC_PER_ROW 25   // 100 floats / 4 per float4

__device__ __forceinline__ void acc_add(float4& a, const float4& v) {
    a.x += v.x; a.y += v.y; a.z += v.z; a.w += v.w;
}

// 32-neighbor fully-unrolled gather: 8 groups x 4 outstanding LDG.E.128.
__device__ __forceinline__
float4 gather32(const float* __restrict__ X, int my_idx,
                bool active, size_t lane_off)
{
    float4 acc = make_float4(0.f, 0.f, 0.f, 0.f);
    #pragma unroll
    for (int g = 0; g < 8; g++) {
        const int j0 = __shfl_sync(0xffffffffu, my_idx, g * 4 + 0);
        const int j1 = __shfl_sync(0xffffffffu, my_idx, g * 4 + 1);
        const int j2 = __shfl_sync(0xffffffffu, my_idx, g * 4 + 2);
        const int j3 = __shfl_sync(0xffffffffu, my_idx, g * 4 + 3);
        if (active) {
            const float4 v0 = *(const float4*)(X + (size_t)j0 * D_DIM + lane_off);
            const float4 v1 = *(const float4*)(X + (size_t)j1 * D_DIM + lane_off);
            const float4 v2 = *(const float4*)(X + (size_t)j2 * D_DIM + lane_off);
            const float4 v3 = *(const float4*)(X + (size_t)j3 * D_DIM + lane_off);
            acc.x += (v0.x + v1.x) + (v2.x + v3.x);
            acc.y += (v0.y + v1.y) + (v2.y + v3.y);
            acc.z += (v0.z + v1.z) + (v2.z + v3.z);
            acc.w += (v0.w + v1.w) + (v2.w + v3.w);
        }
    }
    return acc;
}

// Generic (deg != 32) path: chunks of 32 indices.
template <typename IT>
__device__ __forceinline__
float4 gather_generic(const float* __restrict__ X, const IT* __restrict__ ci,
                      long long start, int deg, int first_idx,
                      int lane, bool active, size_t lane_off)
{
    float4 acc = make_float4(0.f, 0.f, 0.f, 0.f);
    for (int k0 = 0; k0 < deg; k0 += 32) {
        const int cnt = min(32, deg - k0);
        int my_idx = first_idx;
        if (k0 > 0) {
            my_idx = 0;
            if (lane < cnt) my_idx = (int)__ldcs(ci + start + k0 + lane);
        }
        for (int k = 0; k < cnt; k++) {
            const int j = __shfl_sync(0xffffffffu, my_idx, k);
            if (active) {
                const float4 v = *(const float4*)(X + (size_t)j * D_DIM + lane_off);
                acc_add(acc, v);
            }
        }
    }
    return acc;
}

template <typename IT>
__device__ __forceinline__
void run(const float* __restrict__ X, const IT* __restrict__ rp,
         const IT* __restrict__ ci, float* __restrict__ out,
         int n, int warp0, int nwarps, int lane)
{
    const bool active = (lane < VEC_PER_ROW);
    const size_t lane_off = (size_t)lane * 4;

    if (warp0 >= n) return;

    // Stage first row.
    long long start = (long long)rp[warp0];
    int deg = (int)((long long)rp[warp0 + 1] - start);
    int idx = 0;
    if (lane < min(deg, 32)) idx = (int)__ldcs(ci + start + lane);

    for (int row = warp0; row < n; row += nwarps) {
        // Prefetch next row's rp + first index block before the gather body,
        // hiding the dependent startup chain under the current row's
        // ~265 cyc of gather wavefronts. (Live now: ~14 rows per warp.)
        const int next = row + nwarps;
        long long start_n = 0; int deg_n = 0; int idx_n = 0;
        if (next < n) {
            start_n = (long long)rp[next];
            deg_n = (int)((long long)rp[next + 1] - start_n);
            if (lane < min(deg_n, 32)) idx_n = (int)__ldcs(ci + start_n + lane);
        }

        float4 acc;
        if (deg == 32) {
            acc = gather32(X, idx, active, lane_off);
        } else {
            acc = gather_generic<IT>(X, ci, start, deg, idx,
                                     lane, active, lane_off);
        }

        if (active) {
            __stcs((float4*)(out + (size_t)row * D_DIM + lane_off), acc);
        }

        start = start_n; deg = deg_n; idx = idx_n;
    }
}

__global__ __launch_bounds__(256)
void sag_persistent_kernel(const float* __restrict__ X,
                           const void* __restrict__ rp_raw,
                           const void* __restrict__ ci_raw,
                           float* __restrict__ out,
                           int n)
{
    const int lane = threadIdx.x & 31;
    const int warp0 = (blockIdx.x * blockDim.x + threadIdx.x) >> 5;
    const int nwarps = (gridDim.x * blockDim.x) >> 5;

    // Runtime index-width probe: two ALIGNED scalar 4B loads (uniform result).
    // int32 rp: words [0,32,64,...] -> w1 != 0
    // int64 rp: words [0,0,32,0,..] -> w1 == 0 && w2 != 0
    const int* rp_words = (const int*)rp_raw;
    const int w1 = __ldg(rp_words + 1);
    const int w2 = __ldg(rp_words + 2);
    const bool is64 = (w1 == 0) && (w2 != 0);

    if (is64) {
        run<long long>(X, (const long long*)rp_raw, (const long long*)ci_raw,
                       out, n, warp0, nwarps, lane);
    } else {
        run<int>(X, (const int*)rp_raw, (const int*)ci_raw,
                 out, n, warp0, nwarps, lane);
    }
}

extern "C" void kernel_launch(void* const* d_in, const int* in_sizes, int n_in,
                              void* d_out, int out_size)
{
    const float* X   = (const float*)d_in[0];
    const void*  rp  = d_in[1];
    const void*  ci  = d_in[2];
    float*       out = (float*)d_out;

    const int n = in_sizes[1] - 1;           // row_pointers has N+1 entries

    const int threads = 256;                  // 8 warps/block
    // Persistent grid: 6 blocks/SM x 148 SMs = 888 blocks = exactly 1 wave at
    // the measured 38-reg occupancy. Each warp loops ~n/7104 ~ 14 rows.
    const int persistent_blocks = 148 * 6;
    const int warps_per_block = threads / 32;
    const int needed = (n + warps_per_block - 1) / warps_per_block;
    const int blocks = needed < persistent_blocks ? needed : persistent_blocks;

    sag_persistent_kernel<<<blocks, threads>>>(X, rp, ci, out, n);
}